// round 4
// baseline (speedup 1.0000x reference)
#include <cuda_runtime.h>
#include <math.h>

#define BB   16
#define LL   1024
#define DD   384
#define FF   1536
#define TOUT 10240
#define MAXDUR 10

// Scratch (device globals: allocation-free rule)
__device__ float g_h1a[BB*LL*FF];
__device__ float g_h1b[BB*LL*DD];
__device__ float g_h1n[BB*LL*DD];
__device__ float g_h2a[BB*LL*FF];
__device__ float g_h2b[BB*LL*DD];
__device__ int   g_lns[BB*LL];
__device__ int   g_csum[BB*LL];
__device__ int   g_tot[BB];
// Transposed weights: wT[ci*3+k][co]
__device__ float g_w1aT[DD*3*FF];
__device__ float g_w1bT[FF*3*DD];
__device__ float g_w2aT[DD*3*FF];
__device__ float g_w2bT[FF*3*DD];

// ---------------------------------------------------------------------------
// Tiled weight transpose: w[co][r] -> wT[r][co]  (r = ci*3+k).
// 32x32 smem tile, coalesced loads AND stores.
// Grid: (cin3/32, cout/32), block 256.
// ---------------------------------------------------------------------------
__global__ __launch_bounds__(256)
void wtr_kernel(const float* __restrict__ w, float* __restrict__ wT,
                int cout, int cin3)
{
    __shared__ float s[32][33];
    const int tx = threadIdx.x & 31;
    const int ty = threadIdx.x >> 5;      // 0..7
    const int r0 = blockIdx.x * 32;
    const int c0 = blockIdx.y * 32;
#pragma unroll
    for (int j = 0; j < 32; j += 8)
        s[j + ty][tx] = w[(size_t)(c0 + j + ty) * cin3 + r0 + tx];
    __syncthreads();
#pragma unroll
    for (int j = 0; j < 32; j += 8)
        wT[(size_t)(r0 + j + ty) * cout + c0 + tx] = s[tx][j + ty];
}

// ---------------------------------------------------------------------------
// Conv1d (K=3, SAME) + bias + ReLU, GEMM-style.
// Block tile: 128 l-rows x 128 co-cols, 256 threads, 8x8 microtile.
// Weights pre-transposed to wT[ci*3+k][co].
// ---------------------------------------------------------------------------
template<int CIN, int COUT>
__global__ __launch_bounds__(256, 2)
void conv_relu_kernel(const float* __restrict__ in, const float* __restrict__ wT,
                      const float* __restrict__ bias, float* __restrict__ out,
                      const int* __restrict__ tlen, int margin)
{
    const int b     = blockIdx.z;
    const int lbase = blockIdx.x * 128;
    const int cbase = blockIdx.y * 128;
    int limit = tlen[b] + margin; if (limit > LL) limit = LL;
    if (lbase >= limit) return;

    __shared__ float As[16][132];     // [ci][ll], ll in [0,129] -> l = lbase-1+ll
    __shared__ float Ws[16][3][128];  // [ci][k][co], 512B rows

    const int tid = threadIdx.x;
    const int tx  = tid & 15;         // co group: owns co = cbase + tx*8 .. +7
    const int ty  = tid >> 4;         // row group: owns l = lbase + ty*8 .. +7

    float acc[8][8];
#pragma unroll
    for (int i = 0; i < 8; i++)
#pragma unroll
        for (int j = 0; j < 8; j++) acc[i][j] = 0.f;

    const float* inB = in + (size_t)b * LL * CIN;

    for (int cb = 0; cb < CIN; cb += 16) {
        // ---- A tile: 130 rows x 16 ci, float4 over ci. 520 float4s. ----
        for (int i = tid; i < 520; i += 256) {
            int ll = i >> 2, c4 = (i & 3) * 4;
            int gl = lbase + ll - 1;
            float4 v = make_float4(0.f, 0.f, 0.f, 0.f);
            if (gl >= 0 && gl < LL)
                v = *(const float4*)&inB[(size_t)gl * CIN + cb + c4];
            As[c4 + 0][ll] = v.x; As[c4 + 1][ll] = v.y;
            As[c4 + 2][ll] = v.z; As[c4 + 3][ll] = v.w;
        }
        // ---- W tile: 48 rows (ci*3+k) x 128 co = 1536 float4s, 6/thread ----
#pragma unroll
        for (int i = tid; i < 1536; i += 256) {
            int r  = i >> 5;           // 0..47
            int c4 = (i & 31) * 4;
            float4 v = *(const float4*)&wT[((size_t)(cb * 3 + r)) * COUT + cbase + c4];
            *(float4*)&Ws[0][0][(size_t)r * 128 + c4] = v;
        }
        __syncthreads();

#pragma unroll 4
        for (int ci = 0; ci < 16; ci++) {
            float4 a03 = *(const float4*)&As[ci][ty * 8];
            float4 a47 = *(const float4*)&As[ci][ty * 8 + 4];
            float2 a89 = *(const float2*)&As[ci][ty * 8 + 8];
            float a[10] = {a03.x, a03.y, a03.z, a03.w,
                           a47.x, a47.y, a47.z, a47.w,
                           a89.x, a89.y};
            float4 w0a = *(const float4*)&Ws[ci][0][tx * 8];
            float4 w0b = *(const float4*)&Ws[ci][0][tx * 8 + 4];
            float4 w1a = *(const float4*)&Ws[ci][1][tx * 8];
            float4 w1b = *(const float4*)&Ws[ci][1][tx * 8 + 4];
            float4 w2a = *(const float4*)&Ws[ci][2][tx * 8];
            float4 w2b = *(const float4*)&Ws[ci][2][tx * 8 + 4];
            float wv0[8] = {w0a.x, w0a.y, w0a.z, w0a.w, w0b.x, w0b.y, w0b.z, w0b.w};
            float wv1[8] = {w1a.x, w1a.y, w1a.z, w1a.w, w1b.x, w1b.y, w1b.z, w1b.w};
            float wv2[8] = {w2a.x, w2a.y, w2a.z, w2a.w, w2b.x, w2b.y, w2b.z, w2b.w};
#pragma unroll
            for (int i = 0; i < 8; i++)
#pragma unroll
                for (int j = 0; j < 8; j++) {
                    acc[i][j] = fmaf(a[i],     wv0[j], acc[i][j]);
                    acc[i][j] = fmaf(a[i + 1], wv1[j], acc[i][j]);
                    acc[i][j] = fmaf(a[i + 2], wv2[j], acc[i][j]);
                }
        }
        __syncthreads();
    }

    const float4 bva = *(const float4*)&bias[cbase + tx * 8];
    const float4 bvb = *(const float4*)&bias[cbase + tx * 8 + 4];
    const float bv[8] = {bva.x, bva.y, bva.z, bva.w, bvb.x, bvb.y, bvb.z, bvb.w};
#pragma unroll
    for (int i = 0; i < 8; i++) {
        int l = lbase + ty * 8 + i;
        float4 o0, o1;
        o0.x = fmaxf(acc[i][0] + bv[0], 0.f);
        o0.y = fmaxf(acc[i][1] + bv[1], 0.f);
        o0.z = fmaxf(acc[i][2] + bv[2], 0.f);
        o0.w = fmaxf(acc[i][3] + bv[3], 0.f);
        o1.x = fmaxf(acc[i][4] + bv[4], 0.f);
        o1.y = fmaxf(acc[i][5] + bv[5], 0.f);
        o1.z = fmaxf(acc[i][6] + bv[6], 0.f);
        o1.w = fmaxf(acc[i][7] + bv[7], 0.f);
        float* dst = &out[((size_t)b * LL + l) * COUT + cbase + tx * 8];
        *(float4*)dst       = o0;
        *(float4*)(dst + 4) = o1;
    }
}

// ---------------------------------------------------------------------------
// LayerNorm over D=384, one warp per (b,l) row.
// ---------------------------------------------------------------------------
__global__ __launch_bounds__(256)
void ln_kernel(const float* __restrict__ in, const float* __restrict__ g,
               const float* __restrict__ be, float* __restrict__ out,
               const int* __restrict__ tlen, int margin)
{
    int b = blockIdx.y;
    int l = blockIdx.x * 8 + (threadIdx.x >> 5);
    int lane = threadIdx.x & 31;
    int limit = tlen[b] + margin; if (limit > LL) limit = LL;
    if (l >= limit) return;

    size_t base = ((size_t)b * LL + l) * DD;
    float x[12];
#pragma unroll
    for (int i = 0; i < 12; i++) x[i] = in[base + lane + 32 * i];
    float s = 0.f;
#pragma unroll
    for (int i = 0; i < 12; i++) s += x[i];
#pragma unroll
    for (int o = 16; o > 0; o >>= 1) s += __shfl_xor_sync(0xffffffffu, s, o);
    float mu = s * (1.f / DD);
    float q = 0.f;
#pragma unroll
    for (int i = 0; i < 12; i++) { float d = x[i] - mu; q += d * d; }
#pragma unroll
    for (int o = 16; o > 0; o >>= 1) q += __shfl_xor_sync(0xffffffffu, q, o);
    float rstd = 1.f / sqrtf(q * (1.f / DD) + 1e-5f);
#pragma unroll
    for (int i = 0; i < 12; i++) {
        int d = lane + 32 * i;
        out[base + d] = (x[i] - mu) * rstd * g[d] + be[d];
    }
}

// ---------------------------------------------------------------------------
// Fused LN2 + linear (D->1) + durations.
// ---------------------------------------------------------------------------
__global__ __launch_bounds__(256)
void pred_kernel(const float* __restrict__ in, const float* __restrict__ g,
                 const float* __restrict__ be, const float* __restrict__ wl,
                 const float* __restrict__ bl, const int* __restrict__ tlen,
                 int* __restrict__ lns)
{
    int b = blockIdx.y;
    int l = blockIdx.x * 8 + (threadIdx.x >> 5);
    int lane = threadIdx.x & 31;
    if (l >= tlen[b]) { if (lane == 0) lns[b * LL + l] = 0; return; }

    size_t base = ((size_t)b * LL + l) * DD;
    float x[12];
#pragma unroll
    for (int i = 0; i < 12; i++) x[i] = in[base + lane + 32 * i];
    float s = 0.f;
#pragma unroll
    for (int i = 0; i < 12; i++) s += x[i];
#pragma unroll
    for (int o = 16; o > 0; o >>= 1) s += __shfl_xor_sync(0xffffffffu, s, o);
    float mu = s * (1.f / DD);
    float q = 0.f;
#pragma unroll
    for (int i = 0; i < 12; i++) { float d = x[i] - mu; q += d * d; }
#pragma unroll
    for (int o = 16; o > 0; o >>= 1) q += __shfl_xor_sync(0xffffffffu, q, o);
    float rstd = 1.f / sqrtf(q * (1.f / DD) + 1e-5f);
    float p = 0.f;
#pragma unroll
    for (int i = 0; i < 12; i++) {
        int d = lane + 32 * i;
        p += ((x[i] - mu) * rstd * g[d] + be[d]) * wl[d];
    }
#pragma unroll
    for (int o = 16; o > 0; o >>= 1) p += __shfl_xor_sync(0xffffffffu, p, o);
    if (lane == 0) {
        float e = expf(p + bl[0]);
        float r = rintf(e);
        if (r > (float)MAXDUR) r = (float)MAXDUR;
        lns[b * LL + l] = (int)r;
    }
}

// ---------------------------------------------------------------------------
// Inclusive scan of durations per batch row.
// ---------------------------------------------------------------------------
__global__ __launch_bounds__(1024)
void scan_kernel(const int* __restrict__ lns, int* __restrict__ csum,
                 int* __restrict__ tot, float* __restrict__ out_tail, int write_tail)
{
    __shared__ int s[1024];
    int b = blockIdx.x, t = threadIdx.x;
    s[t] = lns[b * LL + t];
    __syncthreads();
    for (int o = 1; o < 1024; o <<= 1) {
        int v = (t >= o) ? s[t - o] : 0;
        __syncthreads();
        s[t] += v;
        __syncthreads();
    }
    csum[b * LL + t] = s[t];
    if (t == 1023) {
        tot[b] = s[t];
        if (write_tail) out_tail[b] = (float)s[t];
    }
}

// ---------------------------------------------------------------------------
// Expansion gather.
// ---------------------------------------------------------------------------
__global__ __launch_bounds__(256)
void gather_kernel(const float* __restrict__ y, const int* __restrict__ csum,
                   const int* __restrict__ tot, float* __restrict__ out)
{
    int b = blockIdx.y;
    int t = blockIdx.x * 8 + (threadIdx.x >> 5);
    int lane = threadIdx.x & 31;

    int idx = 0;
    if (lane == 0) {
        const int* c = csum + b * LL;
        int lo = 0, hi = LL;
        while (lo < hi) { int mid = (lo + hi) >> 1; if (c[mid] <= t) lo = mid + 1; else hi = mid; }
        idx = (lo < LL - 1) ? lo : (LL - 1);
    }
    idx = __shfl_sync(0xffffffffu, idx, 0);
    bool valid = t < tot[b];

    const float4* src = (const float4*)(y + ((size_t)b * LL + idx) * DD);
    float4*       dst = (float4*)(out + ((size_t)b * TOUT + t) * DD);
    float4 z = make_float4(0.f, 0.f, 0.f, 0.f);
#pragma unroll
    for (int i = 0; i < 3; i++) dst[lane + 32 * i] = valid ? src[lane + 32 * i] : z;
}

// ---------------------------------------------------------------------------
extern "C" void kernel_launch(void* const* d_in, const int* in_sizes, int n_in,
                              void* d_out, int out_size)
{
    const float* y    = (const float*)d_in[0];
    const int*   tlen = (const int*)  d_in[1];
    const float* w1a  = (const float*)d_in[2];
    const float* b1a  = (const float*)d_in[3];
    const float* w1b  = (const float*)d_in[4];
    const float* b1b  = (const float*)d_in[5];
    const float* g1   = (const float*)d_in[6];
    const float* be1  = (const float*)d_in[7];
    const float* w2a  = (const float*)d_in[8];
    const float* b2a  = (const float*)d_in[9];
    const float* w2b  = (const float*)d_in[10];
    const float* b2b  = (const float*)d_in[11];
    const float* g2   = (const float*)d_in[12];
    const float* be2  = (const float*)d_in[13];
    const float* wl   = (const float*)d_in[14];
    const float* bl   = (const float*)d_in[15];
    float* out = (float*)d_out;

    float *h1a, *h1b, *h1n, *h2a, *h2b; int *lns, *csum, *tot;
    float *w1aT, *w1bT, *w2aT, *w2bT;
    cudaGetSymbolAddress((void**)&h1a, g_h1a);
    cudaGetSymbolAddress((void**)&h1b, g_h1b);
    cudaGetSymbolAddress((void**)&h1n, g_h1n);
    cudaGetSymbolAddress((void**)&h2a, g_h2a);
    cudaGetSymbolAddress((void**)&h2b, g_h2b);
    cudaGetSymbolAddress((void**)&lns, g_lns);
    cudaGetSymbolAddress((void**)&csum, g_csum);
    cudaGetSymbolAddress((void**)&tot, g_tot);
    cudaGetSymbolAddress((void**)&w1aT, g_w1aT);
    cudaGetSymbolAddress((void**)&w1bT, g_w1bT);
    cudaGetSymbolAddress((void**)&w2aT, g_w2aT);
    cudaGetSymbolAddress((void**)&w2bT, g_w2bT);

    // Tiled transposes: w[co][ci*3+k] -> wT[ci*3+k][co]
    wtr_kernel<<<dim3(DD*3/32, FF/32), 256>>>(w1a, w1aT, FF, DD*3);
    wtr_kernel<<<dim3(FF*3/32, DD/32), 256>>>(w1b, w1bT, DD, FF*3);
    wtr_kernel<<<dim3(DD*3/32, FF/32), 256>>>(w2a, w2aT, FF, DD*3);
    wtr_kernel<<<dim3(FF*3/32, DD/32), 256>>>(w2b, w2bT, DD, FF*3);

    dim3 gA(LL / 128, FF / 128, BB);  // D -> F convs
    dim3 gB(LL / 128, DD / 128, BB);  // F -> D convs
    dim3 gR(LL / 8, BB);              // per-row kernels

    conv_relu_kernel<DD, FF><<<gA, 256>>>(y,   w1aT, b1a, h1a, tlen, 3);
    conv_relu_kernel<FF, DD><<<gB, 256>>>(h1a, w1bT, b1b, h1b, tlen, 2);
    ln_kernel<<<gR, 256>>>(h1b, g1, be1, h1n, tlen, 2);
    conv_relu_kernel<DD, FF><<<gA, 256>>>(h1n, w2aT, b2a, h2a, tlen, 1);
    conv_relu_kernel<FF, DD><<<gB, 256>>>(h2a, w2bT, b2b, h2b, tlen, 0);
    pred_kernel<<<gR, 256>>>(h2b, g2, be2, wl, bl, tlen, lns);

    int write_tail = (out_size >= BB * TOUT * DD + BB) ? 1 : 0;
    scan_kernel<<<BB, 1024>>>(lns, csum, tot, out + (size_t)BB * TOUT * DD, write_tail);
    gather_kernel<<<dim3(TOUT / 8, BB), 256>>>(y, csum, tot, out);
}

// round 6
// speedup vs baseline: 1.1315x; 1.1315x over previous
#include <cuda_runtime.h>
#include <math.h>

#define BB   16
#define LL   1024
#define DD   384
#define FF   1536
#define TOUT 10240
#define MAXDUR 10

// Scratch (device globals: allocation-free rule)
__device__ float g_h1a[BB*LL*FF];
__device__ float g_h1b[BB*LL*DD];
__device__ float g_h1n[BB*LL*DD];
__device__ float g_h2a[BB*LL*FF];
__device__ float g_h2b[BB*LL*DD];
__device__ int   g_lns[BB*LL];
__device__ int   g_csum[BB*LL];
__device__ int   g_tot[BB];
// Transposed weights: wT[ci*3+k][co]
__device__ float g_w1aT[DD*3*FF];
__device__ float g_w1bT[FF*3*DD];
__device__ float g_w2aT[DD*3*FF];
__device__ float g_w2bT[FF*3*DD];

// ---------------------------------------------------------------------------
// Tiled weight transpose: w[co][r] -> wT[r][co]  (r = ci*3+k).
// 32x32 smem tile, coalesced loads AND stores.
// ---------------------------------------------------------------------------
__global__ __launch_bounds__(256)
void wtr_kernel(const float* __restrict__ w, float* __restrict__ wT,
                int cout, int cin3)
{
    __shared__ float s[32][33];
    const int tx = threadIdx.x & 31;
    const int ty = threadIdx.x >> 5;
    const int r0 = blockIdx.x * 32;
    const int c0 = blockIdx.y * 32;
#pragma unroll
    for (int j = 0; j < 32; j += 8)
        s[j + ty][tx] = w[(size_t)(c0 + j + ty) * cin3 + r0 + tx];
    __syncthreads();
#pragma unroll
    for (int j = 0; j < 32; j += 8)
        wT[(size_t)(r0 + j + ty) * cout + c0 + tx] = s[tx][j + ty];
}

// ---------------------------------------------------------------------------
// Conv1d (K=3, SAME) + bias + ReLU, GEMM-style.
// Block tile: 128 l-rows x 64 co-cols, 256 threads, 8x4 microtile (R2 config),
// with software-pipelined register prefetch of the next ci-slice so LDG
// latency is hidden under the FMA phase instead of being barrier-exposed.
// ---------------------------------------------------------------------------
template<int CIN, int COUT>
__global__ __launch_bounds__(256)
void conv_relu_kernel(const float* __restrict__ in, const float* __restrict__ wT,
                      const float* __restrict__ bias, float* __restrict__ out,
                      const int* __restrict__ tlen, int margin)
{
    const int b     = blockIdx.z;
    const int lbase = blockIdx.x * 128;
    const int cbase = blockIdx.y * 64;
    int limit = tlen[b] + margin; if (limit > LL) limit = LL;
    if (lbase >= limit) return;

    __shared__ float As[16][132];    // [ci][ll], ll in [0,129] -> l = lbase-1+ll
    __shared__ float Ws[16][3][64];  // [ci][k][co]

    const int tid = threadIdx.x;
    const int tx  = tid & 15;        // co group: owns co = cbase + tx*4 .. +3
    const int ty  = tid >> 4;        // row group: owns l = lbase + ty*8 .. +7

    float acc[8][4];
#pragma unroll
    for (int i = 0; i < 8; i++)
#pragma unroll
        for (int j = 0; j < 4; j++) acc[i][j] = 0.f;

    const float* inB = in + (size_t)b * LL * CIN;

    // Per-thread prefetch slots.
    // A tile: 520 float4 -> tid, tid+256, (tid+512 if tid<8)
    // W tile: 768 float4 -> tid, tid+256, tid+512
    float4 pa0, pa1, pa2, pw0, pw1, pw2;
    const bool hasA2 = (tid < 8);

    // A-element geometry (constant across cb)
    const int llA0 = tid >> 2,         c4A0 = (tid & 3) * 4;
    const int llA1 = (tid + 256) >> 2, c4A1 = ((tid + 256) & 3) * 4;
    const int llA2 = (tid + 512) >> 2, c4A2 = ((tid + 512) & 3) * 4;
    const int glA0 = lbase + llA0 - 1;
    const int glA1 = lbase + llA1 - 1;
    const int glA2 = lbase + llA2 - 1;
    // W-element geometry
    const int rW0 = tid >> 4,          c4W0 = (tid & 15) * 4;
    const int rW1 = (tid + 256) >> 4,  c4W1 = ((tid + 256) & 15) * 4;
    const int rW2 = (tid + 512) >> 4,  c4W2 = ((tid + 512) & 15) * 4;

#define PREFETCH(cb)                                                          \
    do {                                                                      \
        pa0 = make_float4(0.f, 0.f, 0.f, 0.f);                                \
        pa1 = make_float4(0.f, 0.f, 0.f, 0.f);                                \
        pa2 = make_float4(0.f, 0.f, 0.f, 0.f);                                \
        if (glA0 >= 0 && glA0 < LL)                                           \
            pa0 = *(const float4*)&inB[(size_t)glA0 * CIN + (cb) + c4A0];     \
        if (glA1 >= 0 && glA1 < LL)                                           \
            pa1 = *(const float4*)&inB[(size_t)glA1 * CIN + (cb) + c4A1];     \
        if (hasA2 && glA2 >= 0 && glA2 < LL)                                  \
            pa2 = *(const float4*)&inB[(size_t)glA2 * CIN + (cb) + c4A2];     \
        pw0 = *(const float4*)&wT[((size_t)((cb) * 3 + rW0)) * COUT + cbase + c4W0]; \
        pw1 = *(const float4*)&wT[((size_t)((cb) * 3 + rW1)) * COUT + cbase + c4W1]; \
        pw2 = *(const float4*)&wT[((size_t)((cb) * 3 + rW2)) * COUT + cbase + c4W2]; \
    } while (0)

#define STORE_TILE()                                                          \
    do {                                                                      \
        As[c4A0 + 0][llA0] = pa0.x; As[c4A0 + 1][llA0] = pa0.y;               \
        As[c4A0 + 2][llA0] = pa0.z; As[c4A0 + 3][llA0] = pa0.w;               \
        As[c4A1 + 0][llA1] = pa1.x; As[c4A1 + 1][llA1] = pa1.y;               \
        As[c4A1 + 2][llA1] = pa1.z; As[c4A1 + 3][llA1] = pa1.w;               \
        if (hasA2) {                                                          \
            As[c4A2 + 0][llA2] = pa2.x; As[c4A2 + 1][llA2] = pa2.y;           \
            As[c4A2 + 2][llA2] = pa2.z; As[c4A2 + 3][llA2] = pa2.w;           \
        }                                                                     \
        *(float4*)&Ws[0][0][(size_t)rW0 * 64 + c4W0] = pw0;                   \
        *(float4*)&Ws[0][0][(size_t)rW1 * 64 + c4W1] = pw1;                   \
        *(float4*)&Ws[0][0][(size_t)rW2 * 64 + c4W2] = pw2;                   \
    } while (0)

    // Prologue: load first slice
    PREFETCH(0);
    STORE_TILE();
    __syncthreads();

    for (int cb = 0; cb < CIN; cb += 16) {
        const bool has_next = (cb + 16 < CIN);
        if (has_next) PREFETCH(cb + 16);

#pragma unroll 4
        for (int ci = 0; ci < 16; ci++) {
            float4 a03 = *(const float4*)&As[ci][ty * 8];
            float4 a47 = *(const float4*)&As[ci][ty * 8 + 4];
            float2 a89 = *(const float2*)&As[ci][ty * 8 + 8];
            float a[10] = {a03.x, a03.y, a03.z, a03.w,
                           a47.x, a47.y, a47.z, a47.w,
                           a89.x, a89.y};
            float4 w0 = *(const float4*)&Ws[ci][0][tx * 4];
            float4 w1 = *(const float4*)&Ws[ci][1][tx * 4];
            float4 w2 = *(const float4*)&Ws[ci][2][tx * 4];
            float wv0[4] = {w0.x, w0.y, w0.z, w0.w};
            float wv1[4] = {w1.x, w1.y, w1.z, w1.w};
            float wv2[4] = {w2.x, w2.y, w2.z, w2.w};
#pragma unroll
            for (int i = 0; i < 8; i++)
#pragma unroll
                for (int j = 0; j < 4; j++) {
                    acc[i][j] = fmaf(a[i],     wv0[j], acc[i][j]);
                    acc[i][j] = fmaf(a[i + 1], wv1[j], acc[i][j]);
                    acc[i][j] = fmaf(a[i + 2], wv2[j], acc[i][j]);
                }
        }

        if (has_next) {
            __syncthreads();
            STORE_TILE();
            __syncthreads();
        }
    }
#undef PREFETCH
#undef STORE_TILE

    const float4 bv = *(const float4*)&bias[cbase + tx * 4];
#pragma unroll
    for (int i = 0; i < 8; i++) {
        int l = lbase + ty * 8 + i;
        float4 o;
        o.x = fmaxf(acc[i][0] + bv.x, 0.f);
        o.y = fmaxf(acc[i][1] + bv.y, 0.f);
        o.z = fmaxf(acc[i][2] + bv.z, 0.f);
        o.w = fmaxf(acc[i][3] + bv.w, 0.f);
        *(float4*)&out[((size_t)b * LL + l) * COUT + cbase + tx * 4] = o;
    }
}

// ---------------------------------------------------------------------------
// LayerNorm over D=384, one warp per (b,l) row.
// ---------------------------------------------------------------------------
__global__ __launch_bounds__(256)
void ln_kernel(const float* __restrict__ in, const float* __restrict__ g,
               const float* __restrict__ be, float* __restrict__ out,
               const int* __restrict__ tlen, int margin)
{
    int b = blockIdx.y;
    int l = blockIdx.x * 8 + (threadIdx.x >> 5);
    int lane = threadIdx.x & 31;
    int limit = tlen[b] + margin; if (limit > LL) limit = LL;
    if (l >= limit) return;

    size_t base = ((size_t)b * LL + l) * DD;
    float x[12];
#pragma unroll
    for (int i = 0; i < 12; i++) x[i] = in[base + lane + 32 * i];
    float s = 0.f;
#pragma unroll
    for (int i = 0; i < 12; i++) s += x[i];
#pragma unroll
    for (int o = 16; o > 0; o >>= 1) s += __shfl_xor_sync(0xffffffffu, s, o);
    float mu = s * (1.f / DD);
    float q = 0.f;
#pragma unroll
    for (int i = 0; i < 12; i++) { float d = x[i] - mu; q += d * d; }
#pragma unroll
    for (int o = 16; o > 0; o >>= 1) q += __shfl_xor_sync(0xffffffffu, q, o);
    float rstd = 1.f / sqrtf(q * (1.f / DD) + 1e-5f);
#pragma unroll
    for (int i = 0; i < 12; i++) {
        int d = lane + 32 * i;
        out[base + d] = (x[i] - mu) * rstd * g[d] + be[d];
    }
}

// ---------------------------------------------------------------------------
// Fused LN2 + linear (D->1) + durations.
// ---------------------------------------------------------------------------
__global__ __launch_bounds__(256)
void pred_kernel(const float* __restrict__ in, const float* __restrict__ g,
                 const float* __restrict__ be, const float* __restrict__ wl,
                 const float* __restrict__ bl, const int* __restrict__ tlen,
                 int* __restrict__ lns)
{
    int b = blockIdx.y;
    int l = blockIdx.x * 8 + (threadIdx.x >> 5);
    int lane = threadIdx.x & 31;
    if (l >= tlen[b]) { if (lane == 0) lns[b * LL + l] = 0; return; }

    size_t base = ((size_t)b * LL + l) * DD;
    float x[12];
#pragma unroll
    for (int i = 0; i < 12; i++) x[i] = in[base + lane + 32 * i];
    float s = 0.f;
#pragma unroll
    for (int i = 0; i < 12; i++) s += x[i];
#pragma unroll
    for (int o = 16; o > 0; o >>= 1) s += __shfl_xor_sync(0xffffffffu, s, o);
    float mu = s * (1.f / DD);
    float q = 0.f;
#pragma unroll
    for (int i = 0; i < 12; i++) { float d = x[i] - mu; q += d * d; }
#pragma unroll
    for (int o = 16; o > 0; o >>= 1) q += __shfl_xor_sync(0xffffffffu, q, o);
    float rstd = 1.f / sqrtf(q * (1.f / DD) + 1e-5f);
    float p = 0.f;
#pragma unroll
    for (int i = 0; i < 12; i++) {
        int d = lane + 32 * i;
        p += ((x[i] - mu) * rstd * g[d] + be[d]) * wl[d];
    }
#pragma unroll
    for (int o = 16; o > 0; o >>= 1) p += __shfl_xor_sync(0xffffffffu, p, o);
    if (lane == 0) {
        float e = expf(p + bl[0]);
        float r = rintf(e);
        if (r > (float)MAXDUR) r = (float)MAXDUR;
        lns[b * LL + l] = (int)r;
    }
}

// ---------------------------------------------------------------------------
// Inclusive scan of durations per batch row.
// ---------------------------------------------------------------------------
__global__ __launch_bounds__(1024)
void scan_kernel(const int* __restrict__ lns, int* __restrict__ csum,
                 int* __restrict__ tot, float* __restrict__ out_tail, int write_tail)
{
    __shared__ int s[1024];
    int b = blockIdx.x, t = threadIdx.x;
    s[t] = lns[b * LL + t];
    __syncthreads();
    for (int o = 1; o < 1024; o <<= 1) {
        int v = (t >= o) ? s[t - o] : 0;
        __syncthreads();
        s[t] += v;
        __syncthreads();
    }
    csum[b * LL + t] = s[t];
    if (t == 1023) {
        tot[b] = s[t];
        if (write_tail) out_tail[b] = (float)s[t];
    }
}

// ---------------------------------------------------------------------------
// Expansion gather.
// ---------------------------------------------------------------------------
__global__ __launch_bounds__(256)
void gather_kernel(const float* __restrict__ y, const int* __restrict__ csum,
                   const int* __restrict__ tot, float* __restrict__ out)
{
    int b = blockIdx.y;
    int t = blockIdx.x * 8 + (threadIdx.x >> 5);
    int lane = threadIdx.x & 31;

    int idx = 0;
    if (lane == 0) {
        const int* c = csum + b * LL;
        int lo = 0, hi = LL;
        while (lo < hi) { int mid = (lo + hi) >> 1; if (c[mid] <= t) lo = mid + 1; else hi = mid; }
        idx = (lo < LL - 1) ? lo : (LL - 1);
    }
    idx = __shfl_sync(0xffffffffu, idx, 0);
    bool valid = t < tot[b];

    const float4* src = (const float4*)(y + ((size_t)b * LL + idx) * DD);
    float4*       dst = (float4*)(out + ((size_t)b * TOUT + t) * DD);
    float4 z = make_float4(0.f, 0.f, 0.f, 0.f);
#pragma unroll
    for (int i = 0; i < 3; i++) dst[lane + 32 * i] = valid ? src[lane + 32 * i] : z;
}

// ---------------------------------------------------------------------------
extern "C" void kernel_launch(void* const* d_in, const int* in_sizes, int n_in,
                              void* d_out, int out_size)
{
    const float* y    = (const float*)d_in[0];
    const int*   tlen = (const int*)  d_in[1];
    const float* w1a  = (const float*)d_in[2];
    const float* b1a  = (const float*)d_in[3];
    const float* w1b  = (const float*)d_in[4];
    const float* b1b  = (const float*)d_in[5];
    const float* g1   = (const float*)d_in[6];
    const float* be1  = (const float*)d_in[7];
    const float* w2a  = (const float*)d_in[8];
    const float* b2a  = (const float*)d_in[9];
    const float* w2b  = (const float*)d_in[10];
    const float* b2b  = (const float*)d_in[11];
    const float* g2   = (const float*)d_in[12];
    const float* be2  = (const float*)d_in[13];
    const float* wl   = (const float*)d_in[14];
    const float* bl   = (const float*)d_in[15];
    float* out = (float*)d_out;

    float *h1a, *h1b, *h1n, *h2a, *h2b; int *lns, *csum, *tot;
    float *w1aT, *w1bT, *w2aT, *w2bT;
    cudaGetSymbolAddress((void**)&h1a, g_h1a);
    cudaGetSymbolAddress((void**)&h1b, g_h1b);
    cudaGetSymbolAddress((void**)&h1n, g_h1n);
    cudaGetSymbolAddress((void**)&h2a, g_h2a);
    cudaGetSymbolAddress((void**)&h2b, g_h2b);
    cudaGetSymbolAddress((void**)&lns, g_lns);
    cudaGetSymbolAddress((void**)&csum, g_csum);
    cudaGetSymbolAddress((void**)&tot, g_tot);
    cudaGetSymbolAddress((void**)&w1aT, g_w1aT);
    cudaGetSymbolAddress((void**)&w1bT, g_w1bT);
    cudaGetSymbolAddress((void**)&w2aT, g_w2aT);
    cudaGetSymbolAddress((void**)&w2bT, g_w2bT);

    // Tiled transposes: w[co][ci*3+k] -> wT[ci*3+k][co]
    wtr_kernel<<<dim3(DD*3/32, FF/32), 256>>>(w1a, w1aT, FF, DD*3);
    wtr_kernel<<<dim3(FF*3/32, DD/32), 256>>>(w1b, w1bT, DD, FF*3);
    wtr_kernel<<<dim3(DD*3/32, FF/32), 256>>>(w2a, w2aT, FF, DD*3);
    wtr_kernel<<<dim3(FF*3/32, DD/32), 256>>>(w2b, w2bT, DD, FF*3);

    dim3 gA(LL / 128, FF / 64, BB);  // D -> F convs
    dim3 gB(LL / 128, DD / 64, BB);  // F -> D convs
    dim3 gR(LL / 8, BB);             // per-row kernels

    conv_relu_kernel<DD, FF><<<gA, 256>>>(y,   w1aT, b1a, h1a, tlen, 3);
    conv_relu_kernel<FF, DD><<<gB, 256>>>(h1a, w1bT, b1b, h1b, tlen, 2);
    ln_kernel<<<gR, 256>>>(h1b, g1, be1, h1n, tlen, 2);
    conv_relu_kernel<DD, FF><<<gA, 256>>>(h1n, w2aT, b2a, h2a, tlen, 1);
    conv_relu_kernel<FF, DD><<<gB, 256>>>(h2a, w2bT, b2b, h2b, tlen, 0);
    pred_kernel<<<gR, 256>>>(h2b, g2, be2, wl, bl, tlen, lns);

    int write_tail = (out_size >= BB * TOUT * DD + BB) ? 1 : 0;
    scan_kernel<<<BB, 1024>>>(lns, csum, tot, out + (size_t)BB * TOUT * DD, write_tail);
    gather_kernel<<<dim3(TOUT / 8, BB), 256>>>(y, csum, tot, out);
}

// round 7
// speedup vs baseline: 1.1499x; 1.0163x over previous
#include <cuda_runtime.h>
#include <math.h>

#define BB   16
#define LL   1024
#define DD   384
#define FF   1536
#define TOUT 10240
#define MAXDUR 10

typedef unsigned long long u64;

// Scratch (device globals: allocation-free rule)
__device__ float g_h1a[BB*LL*FF];
__device__ float g_h1b[BB*LL*DD];
__device__ float g_h1n[BB*LL*DD];
__device__ float g_h2a[BB*LL*FF];
__device__ float g_h2b[BB*LL*DD];
__device__ int   g_lns[BB*LL];
__device__ int   g_csum[BB*LL];
__device__ int   g_tot[BB];
// Transposed weights: wT[ci*3+k][co]
__device__ float g_w1aT[DD*3*FF];
__device__ float g_w1bT[FF*3*DD];
__device__ float g_w2aT[DD*3*FF];
__device__ float g_w2bT[FF*3*DD];

// ---- packed f32x2 helpers (sm_103a) ----
__device__ __forceinline__ u64 pack2b(float v) {            // (v, v)
    u64 r; asm("mov.b64 %0,{%1,%1};" : "=l"(r) : "f"(v)); return r;
}
__device__ __forceinline__ u64 fma2(u64 a, u64 b, u64 c) {  // per-lane 2x fp32 fma
    u64 d; asm("fma.rn.f32x2 %0,%1,%2,%3;" : "=l"(d) : "l"(a), "l"(b), "l"(c)); return d;
}
__device__ __forceinline__ void unpack2(u64 v, float& lo, float& hi) {
    asm("mov.b64 {%0,%1},%2;" : "=f"(lo), "=f"(hi) : "l"(v));
}

// ---------------------------------------------------------------------------
// Tiled weight transpose: w[co][r] -> wT[r][co]  (r = ci*3+k).
// ---------------------------------------------------------------------------
__global__ __launch_bounds__(256)
void wtr_kernel(const float* __restrict__ w, float* __restrict__ wT,
                int cout, int cin3)
{
    __shared__ float s[32][33];
    const int tx = threadIdx.x & 31;
    const int ty = threadIdx.x >> 5;
    const int r0 = blockIdx.x * 32;
    const int c0 = blockIdx.y * 32;
#pragma unroll
    for (int j = 0; j < 32; j += 8)
        s[j + ty][tx] = w[(size_t)(c0 + j + ty) * cin3 + r0 + tx];
    __syncthreads();
#pragma unroll
    for (int j = 0; j < 32; j += 8)
        wT[(size_t)(r0 + j + ty) * cout + c0 + tx] = s[tx][j + ty];
}

// ---------------------------------------------------------------------------
// Conv1d (K=3, SAME) + bias + ReLU, GEMM-style, packed f32x2 compute.
// Block tile: 128 l-rows x 64 co-cols, 256 threads, 8x4 microtile where the
// 4 co-columns are held as 2 f32x2 accumulators per row.
// ---------------------------------------------------------------------------
template<int CIN, int COUT>
__global__ __launch_bounds__(256)
void conv_relu_kernel(const float* __restrict__ in, const float* __restrict__ wT,
                      const float* __restrict__ bias, float* __restrict__ out,
                      const int* __restrict__ tlen, int margin)
{
    const int b     = blockIdx.z;
    const int lbase = blockIdx.x * 128;
    const int cbase = blockIdx.y * 64;
    int limit = tlen[b] + margin; if (limit > LL) limit = LL;
    if (lbase >= limit) return;

    __shared__ float As[16][132];    // [ci][ll], ll in [0,129] -> l = lbase-1+ll
    __shared__ float Ws[16][3][64];  // [ci][k][co]; rows 16B-aligned

    const int tid = threadIdx.x;
    const int tx  = tid & 15;        // co group: owns co = cbase + tx*4 .. +3
    const int ty  = tid >> 4;        // row group: owns l = lbase + ty*8 .. +7

    u64 acc[8][2];
#pragma unroll
    for (int i = 0; i < 8; i++) { acc[i][0] = 0ull; acc[i][1] = 0ull; }

    const float* inB = in + (size_t)b * LL * CIN;

    for (int cb = 0; cb < CIN; cb += 16) {
        // ---- A tile: 130 rows x 16 ci, float4 over ci. 520 float4s. ----
        for (int i = tid; i < 520; i += 256) {
            int ll = i >> 2, c4 = (i & 3) * 4;
            int gl = lbase + ll - 1;
            float4 v = make_float4(0.f, 0.f, 0.f, 0.f);
            if (gl >= 0 && gl < LL)
                v = *(const float4*)&inB[(size_t)gl * CIN + cb + c4];
            As[c4 + 0][ll] = v.x; As[c4 + 1][ll] = v.y;
            As[c4 + 2][ll] = v.z; As[c4 + 3][ll] = v.w;
        }
        // ---- W tile: 48 rows (ci*3+k) x 64 co = 768 float4s, 3/thread ----
#pragma unroll
        for (int i = tid; i < 768; i += 256) {
            int r = i >> 4;          // 0..47
            int c4 = (i & 15) * 4;
            float4 v = *(const float4*)&wT[((size_t)(cb * 3 + r)) * COUT + cbase + c4];
            *(float4*)&Ws[0][0][(size_t)r * 64 + c4] = v;
        }
        __syncthreads();

#pragma unroll 4
        for (int ci = 0; ci < 16; ci++) {
            // activations: 10 scalars -> 10 broadcast f32x2
            float4 a03 = *(const float4*)&As[ci][ty * 8];
            float4 a47 = *(const float4*)&As[ci][ty * 8 + 4];
            float2 a89 = *(const float2*)&As[ci][ty * 8 + 8];
            u64 ab[10];
            ab[0] = pack2b(a03.x); ab[1] = pack2b(a03.y);
            ab[2] = pack2b(a03.z); ab[3] = pack2b(a03.w);
            ab[4] = pack2b(a47.x); ab[5] = pack2b(a47.y);
            ab[6] = pack2b(a47.z); ab[7] = pack2b(a47.w);
            ab[8] = pack2b(a89.x); ab[9] = pack2b(a89.y);
            // weights: 3 x LDS.128 reinterpreted as 2 f32x2 each (no packing)
            const u64* wp0 = (const u64*)&Ws[ci][0][tx * 4];
            const u64* wp1 = (const u64*)&Ws[ci][1][tx * 4];
            const u64* wp2 = (const u64*)&Ws[ci][2][tx * 4];
            u64 w0[2] = {wp0[0], wp0[1]};
            u64 w1[2] = {wp1[0], wp1[1]};
            u64 w2[2] = {wp2[0], wp2[1]};
#pragma unroll
            for (int i = 0; i < 8; i++)
#pragma unroll
                for (int j = 0; j < 2; j++) {
                    acc[i][j] = fma2(ab[i],     w0[j], acc[i][j]);
                    acc[i][j] = fma2(ab[i + 1], w1[j], acc[i][j]);
                    acc[i][j] = fma2(ab[i + 2], w2[j], acc[i][j]);
                }
        }
        __syncthreads();
    }

    const float4 bv = *(const float4*)&bias[cbase + tx * 4];
#pragma unroll
    for (int i = 0; i < 8; i++) {
        int l = lbase + ty * 8 + i;
        float s0, s1, s2, s3;
        unpack2(acc[i][0], s0, s1);
        unpack2(acc[i][1], s2, s3);
        float4 o;
        o.x = fmaxf(s0 + bv.x, 0.f);
        o.y = fmaxf(s1 + bv.y, 0.f);
        o.z = fmaxf(s2 + bv.z, 0.f);
        o.w = fmaxf(s3 + bv.w, 0.f);
        *(float4*)&out[((size_t)b * LL + l) * COUT + cbase + tx * 4] = o;
    }
}

// ---------------------------------------------------------------------------
// LayerNorm over D=384, one warp per (b,l) row.
// ---------------------------------------------------------------------------
__global__ __launch_bounds__(256)
void ln_kernel(const float* __restrict__ in, const float* __restrict__ g,
               const float* __restrict__ be, float* __restrict__ out,
               const int* __restrict__ tlen, int margin)
{
    int b = blockIdx.y;
    int l = blockIdx.x * 8 + (threadIdx.x >> 5);
    int lane = threadIdx.x & 31;
    int limit = tlen[b] + margin; if (limit > LL) limit = LL;
    if (l >= limit) return;

    size_t base = ((size_t)b * LL + l) * DD;
    float x[12];
#pragma unroll
    for (int i = 0; i < 12; i++) x[i] = in[base + lane + 32 * i];
    float s = 0.f;
#pragma unroll
    for (int i = 0; i < 12; i++) s += x[i];
#pragma unroll
    for (int o = 16; o > 0; o >>= 1) s += __shfl_xor_sync(0xffffffffu, s, o);
    float mu = s * (1.f / DD);
    float q = 0.f;
#pragma unroll
    for (int i = 0; i < 12; i++) { float d = x[i] - mu; q += d * d; }
#pragma unroll
    for (int o = 16; o > 0; o >>= 1) q += __shfl_xor_sync(0xffffffffu, q, o);
    float rstd = 1.f / sqrtf(q * (1.f / DD) + 1e-5f);
#pragma unroll
    for (int i = 0; i < 12; i++) {
        int d = lane + 32 * i;
        out[base + d] = (x[i] - mu) * rstd * g[d] + be[d];
    }
}

// ---------------------------------------------------------------------------
// Fused LN2 + linear (D->1) + durations.
// ---------------------------------------------------------------------------
__global__ __launch_bounds__(256)
void pred_kernel(const float* __restrict__ in, const float* __restrict__ g,
                 const float* __restrict__ be, const float* __restrict__ wl,
                 const float* __restrict__ bl, const int* __restrict__ tlen,
                 int* __restrict__ lns)
{
    int b = blockIdx.y;
    int l = blockIdx.x * 8 + (threadIdx.x >> 5);
    int lane = threadIdx.x & 31;
    if (l >= tlen[b]) { if (lane == 0) lns[b * LL + l] = 0; return; }

    size_t base = ((size_t)b * LL + l) * DD;
    float x[12];
#pragma unroll
    for (int i = 0; i < 12; i++) x[i] = in[base + lane + 32 * i];
    float s = 0.f;
#pragma unroll
    for (int i = 0; i < 12; i++) s += x[i];
#pragma unroll
    for (int o = 16; o > 0; o >>= 1) s += __shfl_xor_sync(0xffffffffu, s, o);
    float mu = s * (1.f / DD);
    float q = 0.f;
#pragma unroll
    for (int i = 0; i < 12; i++) { float d = x[i] - mu; q += d * d; }
#pragma unroll
    for (int o = 16; o > 0; o >>= 1) q += __shfl_xor_sync(0xffffffffu, q, o);
    float rstd = 1.f / sqrtf(q * (1.f / DD) + 1e-5f);
    float p = 0.f;
#pragma unroll
    for (int i = 0; i < 12; i++) {
        int d = lane + 32 * i;
        p += ((x[i] - mu) * rstd * g[d] + be[d]) * wl[d];
    }
#pragma unroll
    for (int o = 16; o > 0; o >>= 1) p += __shfl_xor_sync(0xffffffffu, p, o);
    if (lane == 0) {
        float e = expf(p + bl[0]);
        float r = rintf(e);
        if (r > (float)MAXDUR) r = (float)MAXDUR;
        lns[b * LL + l] = (int)r;
    }
}

// ---------------------------------------------------------------------------
// Inclusive scan of durations per batch row.
// ---------------------------------------------------------------------------
__global__ __launch_bounds__(1024)
void scan_kernel(const int* __restrict__ lns, int* __restrict__ csum,
                 int* __restrict__ tot, float* __restrict__ out_tail, int write_tail)
{
    __shared__ int s[1024];
    int b = blockIdx.x, t = threadIdx.x;
    s[t] = lns[b * LL + t];
    __syncthreads();
    for (int o = 1; o < 1024; o <<= 1) {
        int v = (t >= o) ? s[t - o] : 0;
        __syncthreads();
        s[t] += v;
        __syncthreads();
    }
    csum[b * LL + t] = s[t];
    if (t == 1023) {
        tot[b] = s[t];
        if (write_tail) out_tail[b] = (float)s[t];
    }
}

// ---------------------------------------------------------------------------
// Expansion gather.
// ---------------------------------------------------------------------------
__global__ __launch_bounds__(256)
void gather_kernel(const float* __restrict__ y, const int* __restrict__ csum,
                   const int* __restrict__ tot, float* __restrict__ out)
{
    int b = blockIdx.y;
    int t = blockIdx.x * 8 + (threadIdx.x >> 5);
    int lane = threadIdx.x & 31;

    int idx = 0;
    if (lane == 0) {
        const int* c = csum + b * LL;
        int lo = 0, hi = LL;
        while (lo < hi) { int mid = (lo + hi) >> 1; if (c[mid] <= t) lo = mid + 1; else hi = mid; }
        idx = (lo < LL - 1) ? lo : (LL - 1);
    }
    idx = __shfl_sync(0xffffffffu, idx, 0);
    bool valid = t < tot[b];

    const float4* src = (const float4*)(y + ((size_t)b * LL + idx) * DD);
    float4*       dst = (float4*)(out + ((size_t)b * TOUT + t) * DD);
    float4 z = make_float4(0.f, 0.f, 0.f, 0.f);
#pragma unroll
    for (int i = 0; i < 3; i++) dst[lane + 32 * i] = valid ? src[lane + 32 * i] : z;
}

// ---------------------------------------------------------------------------
extern "C" void kernel_launch(void* const* d_in, const int* in_sizes, int n_in,
                              void* d_out, int out_size)
{
    const float* y    = (const float*)d_in[0];
    const int*   tlen = (const int*)  d_in[1];
    const float* w1a  = (const float*)d_in[2];
    const float* b1a  = (const float*)d_in[3];
    const float* w1b  = (const float*)d_in[4];
    const float* b1b  = (const float*)d_in[5];
    const float* g1   = (const float*)d_in[6];
    const float* be1  = (const float*)d_in[7];
    const float* w2a  = (const float*)d_in[8];
    const float* b2a  = (const float*)d_in[9];
    const float* w2b  = (const float*)d_in[10];
    const float* b2b  = (const float*)d_in[11];
    const float* g2   = (const float*)d_in[12];
    const float* be2  = (const float*)d_in[13];
    const float* wl   = (const float*)d_in[14];
    const float* bl   = (const float*)d_in[15];
    float* out = (float*)d_out;

    float *h1a, *h1b, *h1n, *h2a, *h2b; int *lns, *csum, *tot;
    float *w1aT, *w1bT, *w2aT, *w2bT;
    cudaGetSymbolAddress((void**)&h1a, g_h1a);
    cudaGetSymbolAddress((void**)&h1b, g_h1b);
    cudaGetSymbolAddress((void**)&h1n, g_h1n);
    cudaGetSymbolAddress((void**)&h2a, g_h2a);
    cudaGetSymbolAddress((void**)&h2b, g_h2b);
    cudaGetSymbolAddress((void**)&lns, g_lns);
    cudaGetSymbolAddress((void**)&csum, g_csum);
    cudaGetSymbolAddress((void**)&tot, g_tot);
    cudaGetSymbolAddress((void**)&w1aT, g_w1aT);
    cudaGetSymbolAddress((void**)&w1bT, g_w1bT);
    cudaGetSymbolAddress((void**)&w2aT, g_w2aT);
    cudaGetSymbolAddress((void**)&w2bT, g_w2bT);

    // Tiled transposes: w[co][ci*3+k] -> wT[ci*3+k][co]
    wtr_kernel<<<dim3(DD*3/32, FF/32), 256>>>(w1a, w1aT, FF, DD*3);
    wtr_kernel<<<dim3(FF*3/32, DD/32), 256>>>(w1b, w1bT, DD, FF*3);
    wtr_kernel<<<dim3(DD*3/32, FF/32), 256>>>(w2a, w2aT, FF, DD*3);
    wtr_kernel<<<dim3(FF*3/32, DD/32), 256>>>(w2b, w2bT, DD, FF*3);

    dim3 gA(LL / 128, FF / 64, BB);  // D -> F convs
    dim3 gB(LL / 128, DD / 64, BB);  // F -> D convs
    dim3 gR(LL / 8, BB);             // per-row kernels

    conv_relu_kernel<DD, FF><<<gA, 256>>>(y,   w1aT, b1a, h1a, tlen, 3);
    conv_relu_kernel<FF, DD><<<gB, 256>>>(h1a, w1bT, b1b, h1b, tlen, 2);
    ln_kernel<<<gR, 256>>>(h1b, g1, be1, h1n, tlen, 2);
    conv_relu_kernel<DD, FF><<<gA, 256>>>(h1n, w2aT, b2a, h2a, tlen, 1);
    conv_relu_kernel<FF, DD><<<gB, 256>>>(h2a, w2bT, b2b, h2b, tlen, 0);
    pred_kernel<<<gR, 256>>>(h2b, g2, be2, wl, bl, tlen, lns);

    int write_tail = (out_size >= BB * TOUT * DD + BB) ? 1 : 0;
    scan_kernel<<<BB, 1024>>>(lns, csum, tot, out + (size_t)BB * TOUT * DD, write_tail);
    gather_kernel<<<dim3(TOUT / 8, BB), 256>>>(y, csum, tot, out);
}